// round 15
// baseline (speedup 1.0000x reference)
#include <cuda_runtime.h>
#include <cuda_fp16.h>
#include <cstdint>

#define BB 4
#define SS 4096
#define DD 256
#define NN (BB*SS)

// ---------------- device scratch ----------------
__device__ __half g_src16[NN*DD];
__device__ __half g_Wq16[DD*DD];
__device__ __half g_Wk16[DD*DD];
__device__ __half g_Wv16[DD*DD];
__device__ __half g_Wo16[DD*DD];
__device__ __half g_Qh[NN*DD];
__device__ __half g_Kh[NN*DD];
__device__ __half g_Vth[NN*DD];   // [b][d][s]
__device__ float g_q0[NN];
__device__ float g_k0[NN];

// ---------------- helpers ----------------
#define SWZ(o) ((o) ^ (((o) >> 3) & 0x70))

__device__ __forceinline__ uint32_t smem_u32(const void* p){
    uint32_t a;
    asm("{ .reg .u64 t; cvta.to.shared.u64 t, %1; cvt.u32.u64 %0, t; }" : "=r"(a) : "l"(p));
    return a;
}
__device__ __forceinline__ void cpa16(uint32_t s, const void* g){
    asm volatile("cp.async.cg.shared.global [%0], [%1], 16;" :: "r"(s), "l"(g) : "memory");
}
#define CPA_COMMIT() asm volatile("cp.async.commit_group;" ::: "memory")
#define CPA_WAIT(n)  asm volatile("cp.async.wait_group %0;" :: "n"(n) : "memory")

__device__ __forceinline__ float ex2f(float x){
    float y; asm("ex2.approx.f32 %0, %1;" : "=f"(y) : "f"(x)); return y;
}
__device__ __forceinline__ uint32_t pack_h2(float a, float b){
    __half2 h = __floats2half2_rn(a, b);
    return *reinterpret_cast<uint32_t*>(&h);
}

#define LDMX4(d0,d1,d2,d3,a) \
    asm volatile("ldmatrix.sync.aligned.m8n8.x4.shared.b16 {%0,%1,%2,%3}, [%4];" \
                 : "=r"(d0),"=r"(d1),"=r"(d2),"=r"(d3) : "r"(a))
#define MMA16816(c,a0,a1,a2,a3,b0,b1) \
    asm volatile("mma.sync.aligned.m16n8k16.row.col.f32.f16.f16.f32 " \
                 "{%0,%1,%2,%3},{%4,%5,%6,%7},{%8,%9},{%0,%1,%2,%3};" \
                 : "+f"((c)[0]),"+f"((c)[1]),"+f"((c)[2]),"+f"((c)[3]) \
                 : "r"(a0),"r"(a1),"r"(a2),"r"(a3),"r"(b0),"r"(b1))

// blocked-atom swizzled smem address of 16B chunk (r, c16); apg = atoms per 8-row group
__device__ __forceinline__ uint32_t tadr(uint32_t base, int r, int c16, int apg){
    return base + (uint32_t)(((((r>>3)*apg + (c16>>3))<<10)) +
                             SWZ((uint32_t)(((r&7)<<7) | ((c16&7)<<4))));
}

// ---------------------------------------------------------------------------
// cvt_all: ONE launch converts src + the 4 weight matrices (flat index)
// ---------------------------------------------------------------------------
#define SRC_N4 (NN*DD/4)
#define W_N4   (DD*DD/4)

__global__ __launch_bounds__(256) void cvt_all(
    const float4* __restrict__ src,
    const float4* __restrict__ w0, const float4* __restrict__ w1,
    const float4* __restrict__ w2, const float4* __restrict__ w3,
    uint2* __restrict__ so,
    uint2* __restrict__ o0, uint2* __restrict__ o1,
    uint2* __restrict__ o2, uint2* __restrict__ o3)
{
    int i = blockIdx.x * 256 + threadIdx.x;
    const float4* in; uint2* out; int idx;
    if (i < SRC_N4) { in = src; out = so; idx = i; }
    else {
        int j = i - SRC_N4;
        int w = j >> 14;
        idx = j & 16383;
        switch (w) {
            case 0: in = w0; out = o0; break;
            case 1: in = w1; out = o1; break;
            case 2: in = w2; out = o2; break;
            default: in = w3; out = o3; break;
        }
    }
    float4 v = in[idx];
    out[idx] = make_uint2(pack_h2(v.x, v.y), pack_h2(v.z, v.w));
}

// ---------------------------------------------------------------------------
// shared MMA phase: C(128x128) = A(128x256) W^T, 8-warp 4Mx2N
// ---------------------------------------------------------------------------
__device__ __forceinline__ void mma_phase(
    uint32_t aA, uint32_t bW, int mi, int ni,
    int arow, int asel, int brow, int bsel, float oacc[2][8][4])
{
    #pragma unroll
    for (int m2 = 0; m2 < 2; m2++)
        #pragma unroll
        for (int nf = 0; nf < 8; nf++)
            #pragma unroll
            for (int j = 0; j < 4; j++) oacc[m2][nf][j] = 0.0f;

    #pragma unroll 4
    for (int ks = 0; ks < 16; ks++) {
        uint32_t a[2][4];
        #pragma unroll
        for (int m2 = 0; m2 < 2; m2++)
            LDMX4(a[m2][0],a[m2][1],a[m2][2],a[m2][3],
                  tadr(aA, mi*32 + m2*16 + arow, 2*ks + asel, 4));
        #pragma unroll
        for (int n16 = 0; n16 < 4; n16++) {
            uint32_t b0,b1,b2,b3;
            LDMX4(b0,b1,b2,b3, tadr(bW, ni*64 + n16*16 + brow, 2*ks + bsel, 4));
            #pragma unroll
            for (int m2 = 0; m2 < 2; m2++) {
                MMA16816(oacc[m2][n16*2  ], a[m2][0],a[m2][1],a[m2][2],a[m2][3], b0,b1);
                MMA16816(oacc[m2][n16*2+1], a[m2][0],a[m2][1],a[m2][2],a[m2][3], b2,b3);
            }
        }
    }
}

__device__ __forceinline__ void epi_rowmajor(
    float oacc[2][8][4], const float* bias, __half* outH, float* col0,
    float scale, int i0, int j0, int mi, int ni, int lane)
{
    const int r0 = lane >> 2, cb = lane & 3;
    #pragma unroll
    for (int m2 = 0; m2 < 2; m2++)
        #pragma unroll
        for (int nf = 0; nf < 8; nf++) {
            int r = mi*32 + m2*16 + r0;
            int c = ni*64 + nf*8 + cb*2;
            float b0v = bias[j0 + c], b1v = bias[j0 + c + 1];
            float v00 = oacc[m2][nf][0] + b0v, v01 = oacc[m2][nf][1] + b1v;
            float v10 = oacc[m2][nf][2] + b0v, v11 = oacc[m2][nf][3] + b1v;
            size_t n0 = (size_t)(i0 + r), n1 = n0 + 8;
            if (col0 && j0 + c == 0) { col0[n0] = v00; col0[n1] = v10; }
            reinterpret_cast<uint32_t*>(outH)[(n0*DD + j0 + c) >> 1] =
                pack_h2(v00*scale, v01*scale);
            reinterpret_cast<uint32_t*>(outH)[(n1*DD + j0 + c) >> 1] =
                pack_h2(v10*scale, v11*scale);
        }
}

// ---------------------------------------------------------------------------
// proj_qkv: fused Q/K/V projections (frozen)
// ---------------------------------------------------------------------------
#define QKV_SMEM (196608 + 1024)

__global__ __launch_bounds__(256, 1) void proj_qkv(
    const __half* __restrict__ A16,
    const __half* __restrict__ Wq16, const __half* __restrict__ Wk16,
    const __half* __restrict__ Wv16,
    const float* __restrict__ bq, const float* __restrict__ bk,
    const float* __restrict__ bv,
    __half* __restrict__ Qh, __half* __restrict__ Kh, __half* __restrict__ Vt,
    float* __restrict__ q0, float* __restrict__ k0, float qscale)
{
    extern __shared__ char psm[];
    const uint32_t raw = smem_u32(psm);
    const uint32_t abase = (raw + 1023u) & ~1023u;
    char* cbase = psm + (abase - raw);
    const uint32_t aA = abase;
    const uint32_t aW0 = abase + 65536u, aW1 = abase + 131072u;

    const int tid = threadIdx.x, wid = tid >> 5, lane = tid & 31;
    const int mi = wid >> 1, ni = wid & 1;
    const int i0 = blockIdx.x * 128, j0 = blockIdx.y * 128;

    const int mat = lane >> 3, lr = lane & 7;
    const int arow = (mat & 1) * 8 + lr;
    const int asel = mat >> 1;
    const int brow = ((mat >> 1) << 3) + lr;
    const int bsel = mat & 1;

    const uint4* A4  = reinterpret_cast<const uint4*>(A16);
    const uint4* Wq4 = reinterpret_cast<const uint4*>(Wq16);
    const uint4* Wk4 = reinterpret_cast<const uint4*>(Wk16);
    const uint4* Wv4 = reinterpret_cast<const uint4*>(Wv16);

    #pragma unroll
    for (int t = 0; t < 16; t++) {
        int idx = tid + t * 256;
        int r = idx >> 5, c = idx & 31;
        cpa16(tadr(aA, r, c, 4), A4 + (size_t)(i0 + r)*32 + c);
    }
    CPA_COMMIT();
    #pragma unroll
    for (int t = 0; t < 16; t++) {
        int idx = tid + t * 256;
        int r = idx >> 5, c = idx & 31;
        cpa16(tadr(aW0, r, c, 4), Wq4 + (size_t)(j0 + r)*32 + c);
    }
    CPA_COMMIT();
    #pragma unroll
    for (int t = 0; t < 16; t++) {
        int idx = tid + t * 256;
        int r = idx >> 5, c = idx & 31;
        cpa16(tadr(aW1, r, c, 4), Wk4 + (size_t)(j0 + r)*32 + c);
    }
    CPA_COMMIT();

    float oacc[2][8][4];

    // ---- Q phase ----
    CPA_WAIT(1);
    __syncthreads();
    mma_phase(aA, aW0, mi, ni, arow, asel, brow, bsel, oacc);
    __syncthreads();
    #pragma unroll
    for (int t = 0; t < 16; t++) {
        int idx = tid + t * 256;
        int r = idx >> 5, c = idx & 31;
        cpa16(tadr(aW0, r, c, 4), Wv4 + (size_t)(j0 + r)*32 + c);
    }
    CPA_COMMIT();
    epi_rowmajor(oacc, bq, Qh, q0, qscale, i0, j0, mi, ni, lane);

    // ---- K phase ----
    CPA_WAIT(1);
    __syncthreads();
    mma_phase(aA, aW1, mi, ni, arow, asel, brow, bsel, oacc);
    epi_rowmajor(oacc, bk, Kh, k0, 1.0f, i0, j0, mi, ni, lane);

    // ---- V phase ----
    CPA_WAIT(0);
    __syncthreads();
    mma_phase(aA, aW0, mi, ni, arow, asel, brow, bsel, oacc);

    {
        float* st = reinterpret_cast<float*>(cbase + 131072);
        const int r0 = lane >> 2, cb = lane & 3;
        const int b = i0 >> 12, s0 = i0 & 4095;
        uint4* V4o = reinterpret_cast<uint4*>(Vt);
        #pragma unroll
        for (int p = 0; p < 2; p++) {
            __syncthreads();
            if ((mi >> 1) == p) {
                #pragma unroll
                for (int m2 = 0; m2 < 2; m2++)
                    #pragma unroll
                    for (int nf = 0; nf < 8; nf++) {
                        int r = (mi & 1)*32 + m2*16 + r0;
                        int c = ni*64 + nf*8 + cb*2;
                        float b0v = bv[j0 + c], b1v = bv[j0 + c + 1];
                        st[r*129 + c]       = oacc[m2][nf][0] + b0v;
                        st[r*129 + c + 1]   = oacc[m2][nf][1] + b1v;
                        st[(r+8)*129 + c]   = oacc[m2][nf][2] + b0v;
                        st[(r+8)*129 + c+1] = oacc[m2][nf][3] + b1v;
                    }
            }
            __syncthreads();
            #pragma unroll
            for (int t = 0; t < 4; t++) {
                int idx = tid + t * 256;
                int dl = idx >> 3, sc = idx & 7;
                uint32_t hh[4];
                #pragma unroll
                for (int e = 0; e < 4; e++)
                    hh[e] = pack_h2(st[(sc*8 + 2*e)*129 + dl],
                                    st[(sc*8 + 2*e + 1)*129 + dl]);
                V4o[((size_t)(b*DD + j0 + dl))*512 + (s0 >> 3) + p*8 + sc] =
                    make_uint4(hh[0], hh[1], hh[2], hh[3]);
            }
        }
    }
}

// ---------------------------------------------------------------------------
// flash_mma v6: BM=64, 128 threads (4 warps M-split), 2 CTAs/SM.
// No smem ping-pong — the co-resident CTA hides load/sync phases.
// Register-P, fused Wo epilogue in two 64KB halves through dead K+V smem.
// SMEM per CTA: Q 32K | K 32K | V 32K = 96K (+pad) -> 2 CTAs/SM.
// ---------------------------------------------------------------------------
#define OFF_Q2   0u
#define OFF_K2   32768u
#define OFF_V2   65536u
#define FL2_SMEM (98304 + 1024)

__global__ __launch_bounds__(128, 2) void flash_mma(
    const __half* __restrict__ Qh_, const __half* __restrict__ Kh_,
    const __half* __restrict__ Vth_, const __half* __restrict__ Wo16_,
    const float* __restrict__ q0g, const float* __restrict__ k0g,
    const float* __restrict__ bo, float* __restrict__ outF)
{
    extern __shared__ char fsm[];
    const uint32_t raw = smem_u32(fsm);
    const uint32_t abase = (raw + 1023u) & ~1023u;
    const uint32_t aQ = abase + OFF_Q2;
    const uint32_t aK = abase + OFF_K2;
    const uint32_t aV = abase + OFF_V2;
    const uint32_t aWo = abase + OFF_K2;   // 64KB spanning K..V after loop

    const int tid = threadIdx.x, wid = tid >> 5, lane = tid & 31;
    const int b = blockIdx.y, i0 = blockIdx.x * 64;

    const int mat = lane >> 3, lr = lane & 7;
    const int arow = (mat & 1) * 8 + lr;
    const int asel = mat >> 1;
    const int brow = ((mat >> 1) << 3) + lr;
    const int bsel = mat & 1;

    const uint4* Qg4 = reinterpret_cast<const uint4*>(Qh_) + ((size_t)(b*SS + i0)) * 32;
    const uint4* Kg4 = reinterpret_cast<const uint4*>(Kh_) + (size_t)b*SS*32;
    const uint4* Vg4 = reinterpret_cast<const uint4*>(Vth_) + (size_t)b*DD*512;
    const uint4* Wo4 = reinterpret_cast<const uint4*>(Wo16_);

    // preload mask inputs
    const int r0 = lane >> 2, cb = lane & 3;
    size_t g0 = (size_t)b*SS + i0 + wid*16 + r0;
    size_t g1 = g0 + 8;
    float q0v0 = q0g[g0], k0v0 = k0g[g0];
    float q0v1 = q0g[g1], k0v1 = k0g[g1];

    // Q tile: 64 rows x 32 chunks
    #pragma unroll
    for (int t = 0; t < 16; t++) {
        int idx = tid + t * 128;
        int r = idx >> 5, c = idx & 31;
        cpa16(tadr(aQ, r, c, 4), Qg4 + (size_t)r*32 + c);
    }
    CPA_COMMIT();

    float oacc[32][4];
    #pragma unroll
    for (int nf = 0; nf < 32; nf++)
        #pragma unroll
        for (int j = 0; j < 4; j++) oacc[nf][j] = 0.0f;
    float lsum0 = 0.0f, lsum1 = 0.0f;

    const int qrow = wid*16 + arow;

    for (int kt = 0; kt < SS/64; kt++) {
        __syncthreads();               // prev tile compute done reading K/V
        // K tile: 64 rows x 32 chunks
        #pragma unroll
        for (int t = 0; t < 16; t++) {
            int idx = tid + t * 128;
            int r = idx >> 5, c = idx & 31;
            cpa16(tadr(aK, r, c, 4), Kg4 + (size_t)(kt*64 + r)*32 + c);
        }
        // V tile: 256 rows x 8 chunks
        #pragma unroll
        for (int t = 0; t < 16; t++) {
            int idx = tid + t * 128;
            int r = idx >> 3, c = idx & 7;
            cpa16(tadr(aV, r, c, 1), Vg4 + (size_t)r*512 + kt*8 + c);
        }
        CPA_COMMIT();
        CPA_WAIT(0);
        __syncthreads();

        // ---- MMA1: S(16x64) = Q K^T ----
        float sacc[8][4];
        #pragma unroll
        for (int n8 = 0; n8 < 8; n8++)
            #pragma unroll
            for (int j = 0; j < 4; j++) sacc[n8][j] = 0.0f;

        #pragma unroll 4
        for (int ks = 0; ks < 16; ks++) {
            uint32_t a0,a1,a2,a3;
            LDMX4(a0,a1,a2,a3, tadr(aQ, qrow, 2*ks + asel, 4));
            #pragma unroll
            for (int n16 = 0; n16 < 4; n16++) {
                uint32_t b0,b1,b2,b3;
                LDMX4(b0,b1,b2,b3, tadr(aK, n16*16 + brow, 2*ks + bsel, 4));
                MMA16816(sacc[n16*2  ], a0,a1,a2,a3, b0,b1);
                MMA16816(sacc[n16*2+1], a0,a1,a2,a3, b2,b3);
            }
        }

        // ---- softmax in registers -> A-fragments ----
        uint32_t pf[4][4];
        #pragma unroll
        for (int n8 = 0; n8 < 8; n8++) {
            float e0 = ex2f(sacc[n8][0]);
            float e1 = ex2f(sacc[n8][1]);
            float e2 = ex2f(sacc[n8][2]);
            float e3 = ex2f(sacc[n8][3]);
            lsum0 += e0 + e1;
            lsum1 += e2 + e3;
            pf[n8 >> 1][(n8 & 1)*2    ] = pack_h2(e0, e1);
            pf[n8 >> 1][(n8 & 1)*2 + 1] = pack_h2(e2, e3);
        }

        // ---- MMA2: O(16x256) += P V ----
        #pragma unroll
        for (int ks = 0; ks < 4; ks++) {
            #pragma unroll
            for (int n16 = 0; n16 < 16; n16++) {
                uint32_t b0,b1,b2,b3;
                LDMX4(b0,b1,b2,b3, tadr(aV, n16*16 + brow, 2*ks + bsel, 1));
                MMA16816(oacc[n16*2  ], pf[ks][0],pf[ks][1],pf[ks][2],pf[ks][3], b0,b1);
                MMA16816(oacc[n16*2+1], pf[ks][0],pf[ks][1],pf[ks][2],pf[ks][3], b2,b3);
            }
        }
    }

    // ---- epilogue: lsum reduce, mask, O -> fp16 A-fragments ----
    lsum0 += __shfl_xor_sync(0xffffffff, lsum0, 1);
    lsum0 += __shfl_xor_sync(0xffffffff, lsum0, 2);
    lsum1 += __shfl_xor_sync(0xffffffff, lsum1, 1);
    lsum1 += __shfl_xor_sync(0xffffffff, lsum1, 2);

    float mf0 = (q0v0 != 0.0f && k0v0 != 0.0f) ? (1.0f / lsum0) : 0.0f;
    float mf1 = (q0v1 != 0.0f && k0v1 != 0.0f) ? (1.0f / lsum1) : 0.0f;

    uint32_t af[16][4];
    #pragma unroll
    for (int nf = 0; nf < 32; nf++) {
        const int ks = nf >> 1;
        af[ks][(nf & 1)*2    ] = pack_h2(oacc[nf][0]*mf0, oacc[nf][1]*mf0);
        af[ks][(nf & 1)*2 + 1] = pack_h2(oacc[nf][2]*mf1, oacc[nf][3]*mf1);
    }

    // ---- fused Wo projection in two 64KB halves ----
    float2* O0 = reinterpret_cast<float2*>(outF + g0*DD);
    float2* O1 = reinterpret_cast<float2*>(outF + g1*DD);

    #pragma unroll
    for (int half = 0; half < 2; half++) {
        __syncthreads();               // all warps done with K/V (or prev half)
        #pragma unroll
        for (int t = 0; t < 32; t++) {
            int idx = tid + t * 128;   // 0..4095 (128 rows x 32 chunks)
            int r = idx >> 5, c = idx & 31;
            cpa16(tadr(aWo, r, c, 4), Wo4 + (size_t)(half*128 + r)*32 + c);
        }
        CPA_COMMIT();
        CPA_WAIT(0);
        __syncthreads();

        float outa[16][4];
        #pragma unroll
        for (int nf = 0; nf < 16; nf++)
            #pragma unroll
            for (int j = 0; j < 4; j++) outa[nf][j] = 0.0f;

        #pragma unroll 4
        for (int ks = 0; ks < 16; ks++) {
            #pragma unroll
            for (int n16 = 0; n16 < 8; n16++) {
                uint32_t b0,b1,b2,b3;
                LDMX4(b0,b1,b2,b3, tadr(aWo, n16*16 + brow, 2*ks + bsel, 4));
                MMA16816(outa[n16*2  ], af[ks][0],af[ks][1],af[ks][2],af[ks][3], b0,b1);
                MMA16816(outa[n16*2+1], af[ks][0],af[ks][1],af[ks][2],af[ks][3], b2,b3);
            }
        }

        #pragma unroll
        for (int nf = 0; nf < 16; nf++) {
            int c = half*128 + (nf >> 1)*16 + (nf & 1)*8 + cb*2;
            float b0v = bo[c], b1v = bo[c + 1];
            O0[((unsigned)c) >> 1] = make_float2(outa[nf][0] + b0v, outa[nf][1] + b1v);
            O1[((unsigned)c) >> 1] = make_float2(outa[nf][2] + b0v, outa[nf][3] + b1v);
        }
    }
}

// ---------------------------------------------------------------------------
extern "C" void kernel_launch(void* const* d_in, const int* in_sizes, int n_in,
                              void* d_out, int out_size)
{
    const float* src = (const float*)d_in[0];
    const float* Wq  = (const float*)d_in[1];
    const float* bq  = (const float*)d_in[2];
    const float* Wk  = (const float*)d_in[3];
    const float* bk  = (const float*)d_in[4];
    const float* Wv  = (const float*)d_in[5];
    const float* bv  = (const float*)d_in[6];
    const float* Wo  = (const float*)d_in[7];
    const float* bo  = (const float*)d_in[8];
    float* out = (float*)d_out;

    __half *pS,*pWq,*pWk,*pWv,*pWo,*pQ,*pK,*pV;
    float *pq0,*pk0;
    cudaGetSymbolAddress((void**)&pS, g_src16);
    cudaGetSymbolAddress((void**)&pWq, g_Wq16);
    cudaGetSymbolAddress((void**)&pWk, g_Wk16);
    cudaGetSymbolAddress((void**)&pWv, g_Wv16);
    cudaGetSymbolAddress((void**)&pWo, g_Wo16);
    cudaGetSymbolAddress((void**)&pQ, g_Qh);
    cudaGetSymbolAddress((void**)&pK, g_Kh);
    cudaGetSymbolAddress((void**)&pV, g_Vth);
    cudaGetSymbolAddress((void**)&pq0, g_q0);
    cudaGetSymbolAddress((void**)&pk0, g_k0);

    const int total4 = SRC_N4 + 4*W_N4;
    cvt_all<<<(total4 + 255)/256, 256>>>(
        (const float4*)src,
        (const float4*)Wq, (const float4*)Wk, (const float4*)Wv, (const float4*)Wo,
        (uint2*)pS, (uint2*)pWq, (uint2*)pWk, (uint2*)pWv, (uint2*)pWo);

    cudaFuncSetAttribute(proj_qkv, cudaFuncAttributeMaxDynamicSharedMemorySize, QKV_SMEM);
    // Q scale = (1/sqrt(256)) * log2(e) -> softmax becomes raw exp2
    proj_qkv<<<dim3(NN/128, 2), 256, QKV_SMEM>>>(
        pS, pWq, pWk, pWv, bq, bk, bv, pQ, pK, pV, pq0, pk0, 0.0901684761047f);

    cudaFuncSetAttribute(flash_mma, cudaFuncAttributeMaxDynamicSharedMemorySize, FL2_SMEM);
    flash_mma<<<dim3(SS/64, BB), 128, FL2_SMEM>>>(pQ, pK, pV, pWo, pq0, pk0, bo, out);
}

// round 16
// speedup vs baseline: 1.1696x; 1.1696x over previous
#include <cuda_runtime.h>
#include <cuda_fp16.h>
#include <cstdint>

#define BB 4
#define SS 4096
#define DD 256
#define NN (BB*SS)

// ---------------- device scratch ----------------
__device__ __half g_src16[NN*DD];
__device__ __half g_Wq16[DD*DD];
__device__ __half g_Wk16[DD*DD];
__device__ __half g_Wv16[DD*DD];
__device__ __half g_Wo16[DD*DD];
__device__ __half g_Qh[NN*DD];
__device__ __half g_Kh[NN*DD];
__device__ __half g_Vth[NN*DD];   // [b][d][s]
__device__ float g_q0[NN];
__device__ float g_k0[NN];

// ---------------- helpers ----------------
#define SWZ(o) ((o) ^ (((o) >> 3) & 0x70))

__device__ __forceinline__ uint32_t smem_u32(const void* p){
    uint32_t a;
    asm("{ .reg .u64 t; cvta.to.shared.u64 t, %1; cvt.u32.u64 %0, t; }" : "=r"(a) : "l"(p));
    return a;
}
__device__ __forceinline__ void cpa16(uint32_t s, const void* g){
    asm volatile("cp.async.cg.shared.global [%0], [%1], 16;" :: "r"(s), "l"(g) : "memory");
}
#define CPA_COMMIT() asm volatile("cp.async.commit_group;" ::: "memory")
#define CPA_WAIT(n)  asm volatile("cp.async.wait_group %0;" :: "n"(n) : "memory")

__device__ __forceinline__ float ex2f(float x){
    float y; asm("ex2.approx.f32 %0, %1;" : "=f"(y) : "f"(x)); return y;
}
__device__ __forceinline__ uint32_t pack_h2(float a, float b){
    __half2 h = __floats2half2_rn(a, b);
    return *reinterpret_cast<uint32_t*>(&h);
}

#define LDMX4(d0,d1,d2,d3,a) \
    asm volatile("ldmatrix.sync.aligned.m8n8.x4.shared.b16 {%0,%1,%2,%3}, [%4];" \
                 : "=r"(d0),"=r"(d1),"=r"(d2),"=r"(d3) : "r"(a))
#define MMA16816(c,a0,a1,a2,a3,b0,b1) \
    asm volatile("mma.sync.aligned.m16n8k16.row.col.f32.f16.f16.f32 " \
                 "{%0,%1,%2,%3},{%4,%5,%6,%7},{%8,%9},{%0,%1,%2,%3};" \
                 : "+f"((c)[0]),"+f"((c)[1]),"+f"((c)[2]),"+f"((c)[3]) \
                 : "r"(a0),"r"(a1),"r"(a2),"r"(a3),"r"(b0),"r"(b1))

// blocked-atom swizzled smem address of 16B chunk (r, c16); apg = atoms per 8-row group
__device__ __forceinline__ uint32_t tadr(uint32_t base, int r, int c16, int apg){
    return base + (uint32_t)(((((r>>3)*apg + (c16>>3))<<10)) +
                             SWZ((uint32_t)(((r&7)<<7) | ((c16&7)<<4))));
}

// ---------------------------------------------------------------------------
// cvt_all: ONE launch converts src + the 4 weight matrices (flat index)
// ---------------------------------------------------------------------------
#define SRC_N4 (NN*DD/4)
#define W_N4   (DD*DD/4)

__global__ __launch_bounds__(256) void cvt_all(
    const float4* __restrict__ src,
    const float4* __restrict__ w0, const float4* __restrict__ w1,
    const float4* __restrict__ w2, const float4* __restrict__ w3,
    uint2* __restrict__ so,
    uint2* __restrict__ o0, uint2* __restrict__ o1,
    uint2* __restrict__ o2, uint2* __restrict__ o3)
{
    int i = blockIdx.x * 256 + threadIdx.x;
    const float4* in; uint2* out; int idx;
    if (i < SRC_N4) { in = src; out = so; idx = i; }
    else {
        int j = i - SRC_N4;
        int w = j >> 14;            // 16384 f4 per weight
        idx = j & 16383;
        switch (w) {
            case 0: in = w0; out = o0; break;
            case 1: in = w1; out = o1; break;
            case 2: in = w2; out = o2; break;
            default: in = w3; out = o3; break;
        }
    }
    float4 v = in[idx];
    out[idx] = make_uint2(pack_h2(v.x, v.y), pack_h2(v.z, v.w));
}

// ---------------------------------------------------------------------------
// shared MMA phase: C(128x128) = A(128x256) W^T, 8-warp 4Mx2N
// ---------------------------------------------------------------------------
__device__ __forceinline__ void mma_phase(
    uint32_t aA, uint32_t bW, int mi, int ni,
    int arow, int asel, int brow, int bsel, float oacc[2][8][4])
{
    #pragma unroll
    for (int m2 = 0; m2 < 2; m2++)
        #pragma unroll
        for (int nf = 0; nf < 8; nf++)
            #pragma unroll
            for (int j = 0; j < 4; j++) oacc[m2][nf][j] = 0.0f;

    #pragma unroll 4
    for (int ks = 0; ks < 16; ks++) {
        uint32_t a[2][4];
        #pragma unroll
        for (int m2 = 0; m2 < 2; m2++)
            LDMX4(a[m2][0],a[m2][1],a[m2][2],a[m2][3],
                  tadr(aA, mi*32 + m2*16 + arow, 2*ks + asel, 4));
        #pragma unroll
        for (int n16 = 0; n16 < 4; n16++) {
            uint32_t b0,b1,b2,b3;
            LDMX4(b0,b1,b2,b3, tadr(bW, ni*64 + n16*16 + brow, 2*ks + bsel, 4));
            #pragma unroll
            for (int m2 = 0; m2 < 2; m2++) {
                MMA16816(oacc[m2][n16*2  ], a[m2][0],a[m2][1],a[m2][2],a[m2][3], b0,b1);
                MMA16816(oacc[m2][n16*2+1], a[m2][0],a[m2][1],a[m2][2],a[m2][3], b2,b3);
            }
        }
    }
}

// fp16 row-major epilogue with scale + optional col0 capture
__device__ __forceinline__ void epi_rowmajor(
    float oacc[2][8][4], const float* bias, __half* outH, float* col0,
    float scale, int i0, int j0, int mi, int ni, int lane)
{
    const int r0 = lane >> 2, cb = lane & 3;
    #pragma unroll
    for (int m2 = 0; m2 < 2; m2++)
        #pragma unroll
        for (int nf = 0; nf < 8; nf++) {
            int r = mi*32 + m2*16 + r0;
            int c = ni*64 + nf*8 + cb*2;
            float b0v = bias[j0 + c], b1v = bias[j0 + c + 1];
            float v00 = oacc[m2][nf][0] + b0v, v01 = oacc[m2][nf][1] + b1v;
            float v10 = oacc[m2][nf][2] + b0v, v11 = oacc[m2][nf][3] + b1v;
            size_t n0 = (size_t)(i0 + r), n1 = n0 + 8;
            if (col0 && j0 + c == 0) { col0[n0] = v00; col0[n1] = v10; }
            reinterpret_cast<uint32_t*>(outH)[(n0*DD + j0 + c) >> 1] =
                pack_h2(v00*scale, v01*scale);
            reinterpret_cast<uint32_t*>(outH)[(n1*DD + j0 + c) >> 1] =
                pack_h2(v10*scale, v11*scale);
        }
}

// ---------------------------------------------------------------------------
// proj_qkv: fused Q/K/V projections
// ---------------------------------------------------------------------------
#define QKV_SMEM (196608 + 1024)

__global__ __launch_bounds__(256, 1) void proj_qkv(
    const __half* __restrict__ A16,
    const __half* __restrict__ Wq16, const __half* __restrict__ Wk16,
    const __half* __restrict__ Wv16,
    const float* __restrict__ bq, const float* __restrict__ bk,
    const float* __restrict__ bv,
    __half* __restrict__ Qh, __half* __restrict__ Kh, __half* __restrict__ Vt,
    float* __restrict__ q0, float* __restrict__ k0, float qscale)
{
    extern __shared__ char psm[];
    const uint32_t raw = smem_u32(psm);
    const uint32_t abase = (raw + 1023u) & ~1023u;
    char* cbase = psm + (abase - raw);
    const uint32_t aA = abase;
    const uint32_t aW0 = abase + 65536u, aW1 = abase + 131072u;

    const int tid = threadIdx.x, wid = tid >> 5, lane = tid & 31;
    const int mi = wid >> 1, ni = wid & 1;
    const int i0 = blockIdx.x * 128, j0 = blockIdx.y * 128;

    const int mat = lane >> 3, lr = lane & 7;
    const int arow = (mat & 1) * 8 + lr;
    const int asel = mat >> 1;
    const int brow = ((mat >> 1) << 3) + lr;
    const int bsel = mat & 1;

    const uint4* A4  = reinterpret_cast<const uint4*>(A16);
    const uint4* Wq4 = reinterpret_cast<const uint4*>(Wq16);
    const uint4* Wk4 = reinterpret_cast<const uint4*>(Wk16);
    const uint4* Wv4 = reinterpret_cast<const uint4*>(Wv16);

    #pragma unroll
    for (int t = 0; t < 16; t++) {
        int idx = tid + t * 256;
        int r = idx >> 5, c = idx & 31;
        cpa16(tadr(aA, r, c, 4), A4 + (size_t)(i0 + r)*32 + c);
    }
    CPA_COMMIT();
    #pragma unroll
    for (int t = 0; t < 16; t++) {
        int idx = tid + t * 256;
        int r = idx >> 5, c = idx & 31;
        cpa16(tadr(aW0, r, c, 4), Wq4 + (size_t)(j0 + r)*32 + c);
    }
    CPA_COMMIT();
    #pragma unroll
    for (int t = 0; t < 16; t++) {
        int idx = tid + t * 256;
        int r = idx >> 5, c = idx & 31;
        cpa16(tadr(aW1, r, c, 4), Wk4 + (size_t)(j0 + r)*32 + c);
    }
    CPA_COMMIT();

    float oacc[2][8][4];

    // ---- Q phase ----
    CPA_WAIT(1);
    __syncthreads();
    mma_phase(aA, aW0, mi, ni, arow, asel, brow, bsel, oacc);
    __syncthreads();
    #pragma unroll
    for (int t = 0; t < 16; t++) {
        int idx = tid + t * 256;
        int r = idx >> 5, c = idx & 31;
        cpa16(tadr(aW0, r, c, 4), Wv4 + (size_t)(j0 + r)*32 + c);
    }
    CPA_COMMIT();
    epi_rowmajor(oacc, bq, Qh, q0, qscale, i0, j0, mi, ni, lane);

    // ---- K phase ----
    CPA_WAIT(1);
    __syncthreads();
    mma_phase(aA, aW1, mi, ni, arow, asel, brow, bsel, oacc);
    epi_rowmajor(oacc, bk, Kh, k0, 1.0f, i0, j0, mi, ni, lane);

    // ---- V phase ----
    CPA_WAIT(0);
    __syncthreads();
    mma_phase(aA, aW0, mi, ni, arow, asel, brow, bsel, oacc);

    {
        float* st = reinterpret_cast<float*>(cbase + 131072);
        const int r0 = lane >> 2, cb = lane & 3;
        const int b = i0 >> 12, s0 = i0 & 4095;
        uint4* V4o = reinterpret_cast<uint4*>(Vt);
        #pragma unroll
        for (int p = 0; p < 2; p++) {
            __syncthreads();
            if ((mi >> 1) == p) {
                #pragma unroll
                for (int m2 = 0; m2 < 2; m2++)
                    #pragma unroll
                    for (int nf = 0; nf < 8; nf++) {
                        int r = (mi & 1)*32 + m2*16 + r0;
                        int c = ni*64 + nf*8 + cb*2;
                        float b0v = bv[j0 + c], b1v = bv[j0 + c + 1];
                        st[r*129 + c]       = oacc[m2][nf][0] + b0v;
                        st[r*129 + c + 1]   = oacc[m2][nf][1] + b1v;
                        st[(r+8)*129 + c]   = oacc[m2][nf][2] + b0v;
                        st[(r+8)*129 + c+1] = oacc[m2][nf][3] + b1v;
                    }
            }
            __syncthreads();
            #pragma unroll
            for (int t = 0; t < 4; t++) {
                int idx = tid + t * 256;
                int dl = idx >> 3, sc = idx & 7;
                uint32_t hh[4];
                #pragma unroll
                for (int e = 0; e < 4; e++)
                    hh[e] = pack_h2(st[(sc*8 + 2*e)*129 + dl],
                                    st[(sc*8 + 2*e + 1)*129 + dl]);
                V4o[((size_t)(b*DD + j0 + dl))*512 + (s0 >> 3) + p*8 + sc] =
                    make_uint4(hh[0], hh[1], hh[2], hh[3]);
            }
        }
    }
}

// ---------------------------------------------------------------------------
// flash_mma: reg-P M-split flash + fused Wo epilogue, early half-Wo prefetch
// into the dead K0/V0 buffers during the last key tile, q0/k0 preloaded.
// SMEM: Q 64K | K ping-pong 2x32K | V ping-pong 2x32K = 192K (Wo reuses K/V)
// ---------------------------------------------------------------------------
#define OFF_Q    0u
#define OFF_K0   65536u
#define OFF_K1   98304u
#define OFF_V0   131072u
#define OFF_V1   163840u
#define FL_SMEM  (196608 + 1024)

__global__ __launch_bounds__(256, 1) void flash_mma(
    const __half* __restrict__ Qh_, const __half* __restrict__ Kh_,
    const __half* __restrict__ Vth_, const __half* __restrict__ Wo16_,
    const float* __restrict__ q0g, const float* __restrict__ k0g,
    const float* __restrict__ bo, float* __restrict__ outF)
{
    extern __shared__ char fsm[];
    const uint32_t raw = smem_u32(fsm);
    const uint32_t abase = (raw + 1023u) & ~1023u;
    const uint32_t aQ = abase + OFF_Q;
    const uint32_t aK[2] = { abase + OFF_K0, abase + OFF_K1 };
    const uint32_t aV[2] = { abase + OFF_V0, abase + OFF_V1 };
    const uint32_t aWo = abase + OFF_K0;   // 128 KB spanning K0..V1 after loop

    const int tid = threadIdx.x, wid = tid >> 5, lane = tid & 31;
    const int b = blockIdx.y, i0 = blockIdx.x * 128;

    const int mat = lane >> 3, lr = lane & 7;
    const int arow = (mat & 1) * 8 + lr;
    const int asel = mat >> 1;
    const int brow = ((mat >> 1) << 3) + lr;
    const int bsel = mat & 1;

    const uint4* Qg4 = reinterpret_cast<const uint4*>(Qh_) + ((size_t)(b*SS + i0)) * 32;
    const uint4* Kg4 = reinterpret_cast<const uint4*>(Kh_) + (size_t)b*SS*32;
    const uint4* Vg4 = reinterpret_cast<const uint4*>(Vth_) + (size_t)b*DD*512;
    const uint4* Wo4 = reinterpret_cast<const uint4*>(Wo16_);

    // preload mask inputs (overlaps everything)
    const int r0 = lane >> 2, cb = lane & 3;
    size_t g0 = (size_t)b*SS + i0 + wid*16 + r0;
    size_t g1 = g0 + 8;
    float q0v0 = q0g[g0], k0v0 = k0g[g0];
    float q0v1 = q0g[g1], k0v1 = k0g[g1];

    #pragma unroll
    for (int t = 0; t < 16; t++) {
        int idx = tid + t * 256;
        int r = idx >> 5, c = idx & 31;
        cpa16(tadr(aQ, r, c, 4), Qg4 + (size_t)r*32 + c);
    }
    CPA_COMMIT();
    #pragma unroll
    for (int t = 0; t < 8; t++) {
        int idx = tid + t * 256;
        int r = idx >> 5, c = idx & 31;
        cpa16(tadr(aK[0], r, c, 4), Kg4 + (size_t)r*32 + c);
    }
    CPA_COMMIT();
    #pragma unroll
    for (int t = 0; t < 8; t++) {
        int idx = tid + t * 256;
        int r = idx >> 3, c = idx & 7;
        cpa16(tadr(aV[0], r, c, 1), Vg4 + (size_t)r*512 + c);
    }
    CPA_COMMIT();

    float oacc[32][4];
    #pragma unroll
    for (int nf = 0; nf < 32; nf++)
        #pragma unroll
        for (int j = 0; j < 4; j++) oacc[nf][j] = 0.0f;
    float lsum0 = 0.0f, lsum1 = 0.0f;

    const int qrow = wid*16 + arow;

    for (int kt = 0; kt < SS/64; kt++) {
        const int buf = kt & 1;
        __syncthreads();
        if (kt + 1 < SS/64) {
            const int nb = buf ^ 1;
            #pragma unroll
            for (int t = 0; t < 8; t++) {
                int idx = tid + t * 256;
                int r = idx >> 5, c = idx & 31;
                cpa16(tadr(aK[nb], r, c, 4), Kg4 + (size_t)((kt+1)*64 + r)*32 + c);
            }
            CPA_COMMIT();
            #pragma unroll
            for (int t = 0; t < 8; t++) {
                int idx = tid + t * 256;
                int r = idx >> 3, c = idx & 7;
                cpa16(tadr(aV[nb], r, c, 1), Vg4 + (size_t)r*512 + (kt+1)*8 + c);
            }
            CPA_COMMIT();
            CPA_WAIT(2);               // K(kt), V(kt) complete
        } else {
            // last tile (buf=1): K0 & V0 dead -> prefetch Wo rows 0..63,128..191
            #pragma unroll
            for (int t = 0; t < 16; t++) {
                int idx = tid + t * 256;
                int rr = idx >> 5, c = idx & 31;
                int r = ((rr & 64) << 1) | (rr & 63);
                cpa16(tadr(aWo, r, c, 4), Wo4 + (size_t)r*32 + c);
            }
            CPA_COMMIT();
            CPA_WAIT(1);               // K(63), V(63) complete; Wo-p1 in flight
        }
        __syncthreads();

        // ---- Phase A: MMA1 keys 0..31 ----
        float sa[4][4];
        #pragma unroll
        for (int n8 = 0; n8 < 4; n8++)
            #pragma unroll
            for (int j = 0; j < 4; j++) sa[n8][j] = 0.0f;

        #pragma unroll
        for (int ks = 0; ks < 16; ks++) {
            uint32_t a0,a1,a2,a3;
            LDMX4(a0,a1,a2,a3, tadr(aQ, qrow, 2*ks + asel, 4));
            #pragma unroll
            for (int n16 = 0; n16 < 2; n16++) {
                uint32_t b0,b1,b2,b3;
                LDMX4(b0,b1,b2,b3, tadr(aK[buf], n16*16 + brow, 2*ks + bsel, 4));
                MMA16816(sa[n16*2  ], a0,a1,a2,a3, b0,b1);
                MMA16816(sa[n16*2+1], a0,a1,a2,a3, b2,b3);
            }
        }

        // ---- softmax-lo -> pf_lo ----
        uint32_t pfl[2][4];
        #pragma unroll
        for (int n8 = 0; n8 < 4; n8++) {
            float e0 = ex2f(sa[n8][0]);
            float e1 = ex2f(sa[n8][1]);
            float e2 = ex2f(sa[n8][2]);
            float e3 = ex2f(sa[n8][3]);
            lsum0 += e0 + e1;
            lsum1 += e2 + e3;
            pfl[n8 >> 1][(n8 & 1)*2    ] = pack_h2(e0, e1);
            pfl[n8 >> 1][(n8 & 1)*2 + 1] = pack_h2(e2, e3);
        }

        // ---- Phase B (fused): MMA1 keys 32..63 + MMA2 ks 0..1 ----
        float sb[4][4];
        #pragma unroll
        for (int n8 = 0; n8 < 4; n8++)
            #pragma unroll
            for (int j = 0; j < 4; j++) sb[n8][j] = 0.0f;

        #pragma unroll
        for (int ks = 0; ks < 16; ks++) {
            uint32_t a0,a1,a2,a3;
            LDMX4(a0,a1,a2,a3, tadr(aQ, qrow, 2*ks + asel, 4));
            #pragma unroll
            for (int n16 = 0; n16 < 2; n16++) {
                uint32_t b0,b1,b2,b3;
                LDMX4(b0,b1,b2,b3, tadr(aK[buf], (n16+2)*16 + brow, 2*ks + bsel, 4));
                MMA16816(sb[n16*2  ], a0,a1,a2,a3, b0,b1);
                MMA16816(sb[n16*2+1], a0,a1,a2,a3, b2,b3);
            }
            #pragma unroll
            for (int u = 0; u < 2; u++) {
                const int vidx = ks*2 + u;
                const int k2 = vidx >> 4;
                const int nv = vidx & 15;
                uint32_t b0,b1,b2,b3;
                LDMX4(b0,b1,b2,b3, tadr(aV[buf], nv*16 + brow, 2*k2 + bsel, 1));
                MMA16816(oacc[nv*2  ], pfl[k2][0],pfl[k2][1],pfl[k2][2],pfl[k2][3], b0,b1);
                MMA16816(oacc[nv*2+1], pfl[k2][0],pfl[k2][1],pfl[k2][2],pfl[k2][3], b2,b3);
            }
        }

        // ---- softmax-hi -> pf_hi ----
        uint32_t pfh[2][4];
        #pragma unroll
        for (int n8 = 0; n8 < 4; n8++) {
            float e0 = ex2f(sb[n8][0]);
            float e1 = ex2f(sb[n8][1]);
            float e2 = ex2f(sb[n8][2]);
            float e3 = ex2f(sb[n8][3]);
            lsum0 += e0 + e1;
            lsum1 += e2 + e3;
            pfh[n8 >> 1][(n8 & 1)*2    ] = pack_h2(e0, e1);
            pfh[n8 >> 1][(n8 & 1)*2 + 1] = pack_h2(e2, e3);
        }

        // ---- MMA2 tail: ks 2..3 ----
        #pragma unroll
        for (int k2 = 0; k2 < 2; k2++) {
            #pragma unroll
            for (int nv = 0; nv < 16; nv++) {
                uint32_t b0,b1,b2,b3;
                LDMX4(b0,b1,b2,b3, tadr(aV[buf], nv*16 + brow, 2*(k2+2) + bsel, 1));
                MMA16816(oacc[nv*2  ], pfh[k2][0],pfh[k2][1],pfh[k2][2],pfh[k2][3], b0,b1);
                MMA16816(oacc[nv*2+1], pfh[k2][0],pfh[k2][1],pfh[k2][2],pfh[k2][3], b2,b3);
            }
        }
    }

    // ---- fused Wo epilogue ----
    __syncthreads();
    #pragma unroll
    for (int t = 0; t < 16; t++) {
        int idx = tid + t * 256;
        int rr = idx >> 5, c = idx & 31;
        int r = (((rr & 64) << 1) | (rr & 63)) + 64;
        cpa16(tadr(aWo, r, c, 4), Wo4 + (size_t)r*32 + c);
    }
    CPA_COMMIT();

    lsum0 += __shfl_xor_sync(0xffffffff, lsum0, 1);
    lsum0 += __shfl_xor_sync(0xffffffff, lsum0, 2);
    lsum1 += __shfl_xor_sync(0xffffffff, lsum1, 1);
    lsum1 += __shfl_xor_sync(0xffffffff, lsum1, 2);

    float mf0 = (q0v0 != 0.0f && k0v0 != 0.0f) ? (1.0f / lsum0) : 0.0f;
    float mf1 = (q0v1 != 0.0f && k0v1 != 0.0f) ? (1.0f / lsum1) : 0.0f;

    uint32_t af[16][4];
    #pragma unroll
    for (int nf = 0; nf < 32; nf++) {
        const int ks = nf >> 1;
        af[ks][(nf & 1)*2    ] = pack_h2(oacc[nf][0]*mf0, oacc[nf][1]*mf0);
        af[ks][(nf & 1)*2 + 1] = pack_h2(oacc[nf][2]*mf1, oacc[nf][3]*mf1);
    }

    float outa[32][4];
    #pragma unroll
    for (int nf = 0; nf < 32; nf++)
        #pragma unroll
        for (int j = 0; j < 4; j++) outa[nf][j] = 0.0f;

    CPA_WAIT(0);
    __syncthreads();

    #pragma unroll 4
    for (int ks = 0; ks < 16; ks++) {
        #pragma unroll
        for (int n16 = 0; n16 < 16; n16++) {
            uint32_t b0,b1,b2,b3;
            LDMX4(b0,b1,b2,b3, tadr(aWo, n16*16 + brow, 2*ks + bsel, 4));
            MMA16816(outa[n16*2  ], af[ks][0],af[ks][1],af[ks][2],af[ks][3], b0,b1);
            MMA16816(outa[n16*2+1], af[ks][0],af[ks][1],af[ks][2],af[ks][3], b2,b3);
        }
    }

    float2* O0 = reinterpret_cast<float2*>(outF + g0*DD);
    float2* O1 = reinterpret_cast<float2*>(outF + g1*DD);
    #pragma unroll
    for (int nf = 0; nf < 32; nf++) {
        int c = (nf >> 1)*16 + (nf & 1)*8 + cb*2;
        float b0v = bo[c], b1v = bo[c + 1];
        O0[((unsigned)c) >> 1] = make_float2(outa[nf][0] + b0v, outa[nf][1] + b1v);
        O1[((unsigned)c) >> 1] = make_float2(outa[nf][2] + b0v, outa[nf][3] + b1v);
    }
}

// ---------------------------------------------------------------------------
extern "C" void kernel_launch(void* const* d_in, const int* in_sizes, int n_in,
                              void* d_out, int out_size)
{
    const float* src = (const float*)d_in[0];
    const float* Wq  = (const float*)d_in[1];
    const float* bq  = (const float*)d_in[2];
    const float* Wk  = (const float*)d_in[3];
    const float* bk  = (const float*)d_in[4];
    const float* Wv  = (const float*)d_in[5];
    const float* bv  = (const float*)d_in[6];
    const float* Wo  = (const float*)d_in[7];
    const float* bo  = (const float*)d_in[8];
    float* out = (float*)d_out;

    __half *pS,*pWq,*pWk,*pWv,*pWo,*pQ,*pK,*pV;
    float *pq0,*pk0;
    cudaGetSymbolAddress((void**)&pS, g_src16);
    cudaGetSymbolAddress((void**)&pWq, g_Wq16);
    cudaGetSymbolAddress((void**)&pWk, g_Wk16);
    cudaGetSymbolAddress((void**)&pWv, g_Wv16);
    cudaGetSymbolAddress((void**)&pWo, g_Wo16);
    cudaGetSymbolAddress((void**)&pQ, g_Qh);
    cudaGetSymbolAddress((void**)&pK, g_Kh);
    cudaGetSymbolAddress((void**)&pV, g_Vth);
    cudaGetSymbolAddress((void**)&pq0, g_q0);
    cudaGetSymbolAddress((void**)&pk0, g_k0);

    const int total4 = SRC_N4 + 4*W_N4;
    cvt_all<<<(total4 + 255)/256, 256>>>(
        (const float4*)src,
        (const float4*)Wq, (const float4*)Wk, (const float4*)Wv, (const float4*)Wo,
        (uint2*)pS, (uint2*)pWq, (uint2*)pWk, (uint2*)pWv, (uint2*)pWo);

    cudaFuncSetAttribute(proj_qkv, cudaFuncAttributeMaxDynamicSharedMemorySize, QKV_SMEM);
    // Q scale = (1/sqrt(256)) * log2(e) -> softmax becomes raw exp2
    proj_qkv<<<dim3(NN/128, 2), 256, QKV_SMEM>>>(
        pS, pWq, pWk, pWv, bq, bk, bv, pQ, pK, pV, pq0, pk0, 0.0901684761047f);

    cudaFuncSetAttribute(flash_mma, cudaFuncAttributeMaxDynamicSharedMemorySize, FL_SMEM);
    flash_mma<<<dim3(SS/128, BB), 256, FL_SMEM>>>(pQ, pK, pV, pWo, pq0, pk0, bo, out);
}

// round 17
// speedup vs baseline: 1.1741x; 1.0038x over previous
#include <cuda_runtime.h>
#include <cuda_fp16.h>
#include <cstdint>

#define BB 4
#define SS 4096
#define DD 256
#define NN (BB*SS)

// ---------------- device scratch ----------------
__device__ __half g_Wq16[DD*DD];
__device__ __half g_Wk16[DD*DD];
__device__ __half g_Wv16[DD*DD];
__device__ __half g_Wo16[DD*DD];
__device__ __half g_Qh[NN*DD];
__device__ __half g_Kh[NN*DD];
__device__ __half g_Vth[NN*DD];   // [b][d][s]
__device__ float g_q0[NN];
__device__ float g_k0[NN];

// ---------------- helpers ----------------
#define SWZ(o) ((o) ^ (((o) >> 3) & 0x70))

__device__ __forceinline__ uint32_t smem_u32(const void* p){
    uint32_t a;
    asm("{ .reg .u64 t; cvta.to.shared.u64 t, %1; cvt.u32.u64 %0, t; }" : "=r"(a) : "l"(p));
    return a;
}
__device__ __forceinline__ void sts128(uint32_t a, uint4 v){
    asm volatile("st.shared.v4.b32 [%0], {%1,%2,%3,%4};"
                 :: "r"(a), "r"(v.x), "r"(v.y), "r"(v.z), "r"(v.w) : "memory");
}
__device__ __forceinline__ void cpa16(uint32_t s, const void* g){
    asm volatile("cp.async.cg.shared.global [%0], [%1], 16;" :: "r"(s), "l"(g) : "memory");
}
#define CPA_COMMIT() asm volatile("cp.async.commit_group;" ::: "memory")
#define CPA_WAIT(n)  asm volatile("cp.async.wait_group %0;" :: "n"(n) : "memory")

__device__ __forceinline__ float ex2f(float x){
    float y; asm("ex2.approx.f32 %0, %1;" : "=f"(y) : "f"(x)); return y;
}
__device__ __forceinline__ uint32_t pack_h2(float a, float b){
    __half2 h = __floats2half2_rn(a, b);
    return *reinterpret_cast<uint32_t*>(&h);
}

#define LDMX4(d0,d1,d2,d3,a) \
    asm volatile("ldmatrix.sync.aligned.m8n8.x4.shared.b16 {%0,%1,%2,%3}, [%4];" \
                 : "=r"(d0),"=r"(d1),"=r"(d2),"=r"(d3) : "r"(a))
#define MMA16816(c,a0,a1,a2,a3,b0,b1) \
    asm volatile("mma.sync.aligned.m16n8k16.row.col.f32.f16.f16.f32 " \
                 "{%0,%1,%2,%3},{%4,%5,%6,%7},{%8,%9},{%0,%1,%2,%3};" \
                 : "+f"((c)[0]),"+f"((c)[1]),"+f"((c)[2]),"+f"((c)[3]) \
                 : "r"(a0),"r"(a1),"r"(a2),"r"(a3),"r"(b0),"r"(b1))

// blocked-atom swizzled smem address of 16B chunk (r, c16); apg = atoms per 8-row group
__device__ __forceinline__ uint32_t tadr(uint32_t base, int r, int c16, int apg){
    return base + (uint32_t)(((((r>>3)*apg + (c16>>3))<<10)) +
                             SWZ((uint32_t)(((r&7)<<7) | ((c16&7)<<4))));
}

// ---------------------------------------------------------------------------
// cvt_w4: the 4 weight matrices in one launch
// ---------------------------------------------------------------------------
#define W_N4 (DD*DD/4)

__global__ __launch_bounds__(256) void cvt_w4(
    const float4* __restrict__ w0, const float4* __restrict__ w1,
    const float4* __restrict__ w2, const float4* __restrict__ w3,
    uint2* __restrict__ o0, uint2* __restrict__ o1,
    uint2* __restrict__ o2, uint2* __restrict__ o3)
{
    const float4* in; uint2* out;
    switch (blockIdx.y) {
        case 0: in = w0; out = o0; break;
        case 1: in = w1; out = o1; break;
        case 2: in = w2; out = o2; break;
        default: in = w3; out = o3; break;
    }
    int i = blockIdx.x * 256 + threadIdx.x;
    float4 v = in[i];
    out[i] = make_uint2(pack_h2(v.x, v.y), pack_h2(v.z, v.w));
}

// ---------------------------------------------------------------------------
// shared MMA phase: C(128x128) = A(128x256) W^T, 8-warp 4Mx2N
// ---------------------------------------------------------------------------
__device__ __forceinline__ void mma_phase(
    uint32_t aA, uint32_t bW, int mi, int ni,
    int arow, int asel, int brow, int bsel, float oacc[2][8][4])
{
    #pragma unroll
    for (int m2 = 0; m2 < 2; m2++)
        #pragma unroll
        for (int nf = 0; nf < 8; nf++)
            #pragma unroll
            for (int j = 0; j < 4; j++) oacc[m2][nf][j] = 0.0f;

    #pragma unroll 4
    for (int ks = 0; ks < 16; ks++) {
        uint32_t a[2][4];
        #pragma unroll
        for (int m2 = 0; m2 < 2; m2++)
            LDMX4(a[m2][0],a[m2][1],a[m2][2],a[m2][3],
                  tadr(aA, mi*32 + m2*16 + arow, 2*ks + asel, 4));
        #pragma unroll
        for (int n16 = 0; n16 < 4; n16++) {
            uint32_t b0,b1,b2,b3;
            LDMX4(b0,b1,b2,b3, tadr(bW, ni*64 + n16*16 + brow, 2*ks + bsel, 4));
            #pragma unroll
            for (int m2 = 0; m2 < 2; m2++) {
                MMA16816(oacc[m2][n16*2  ], a[m2][0],a[m2][1],a[m2][2],a[m2][3], b0,b1);
                MMA16816(oacc[m2][n16*2+1], a[m2][0],a[m2][1],a[m2][2],a[m2][3], b2,b3);
            }
        }
    }
}

// fp16 row-major epilogue with scale + optional col0 capture
__device__ __forceinline__ void epi_rowmajor(
    float oacc[2][8][4], const float* bias, __half* outH, float* col0,
    float scale, int i0, int j0, int mi, int ni, int lane)
{
    const int r0 = lane >> 2, cb = lane & 3;
    #pragma unroll
    for (int m2 = 0; m2 < 2; m2++)
        #pragma unroll
        for (int nf = 0; nf < 8; nf++) {
            int r = mi*32 + m2*16 + r0;
            int c = ni*64 + nf*8 + cb*2;
            float b0v = bias[j0 + c], b1v = bias[j0 + c + 1];
            float v00 = oacc[m2][nf][0] + b0v, v01 = oacc[m2][nf][1] + b1v;
            float v10 = oacc[m2][nf][2] + b0v, v11 = oacc[m2][nf][3] + b1v;
            size_t n0 = (size_t)(i0 + r), n1 = n0 + 8;
            if (col0 && j0 + c == 0) { col0[n0] = v00; col0[n1] = v10; }
            reinterpret_cast<uint32_t*>(outH)[(n0*DD + j0 + c) >> 1] =
                pack_h2(v00*scale, v01*scale);
            reinterpret_cast<uint32_t*>(outH)[(n1*DD + j0 + c) >> 1] =
                pack_h2(v10*scale, v11*scale);
        }
}

// ---------------------------------------------------------------------------
// proj_qkv: fused Q/K/V projections; A read directly from fp32 src and
// converted in-register during smem staging (no separate src cvt kernel).
// ---------------------------------------------------------------------------
#define QKV_SMEM (196608 + 1024)

__global__ __launch_bounds__(256, 1) void proj_qkv(
    const float* __restrict__ Asrc,
    const __half* __restrict__ Wq16, const __half* __restrict__ Wk16,
    const __half* __restrict__ Wv16,
    const float* __restrict__ bq, const float* __restrict__ bk,
    const float* __restrict__ bv,
    __half* __restrict__ Qh, __half* __restrict__ Kh, __half* __restrict__ Vt,
    float* __restrict__ q0, float* __restrict__ k0, float qscale)
{
    extern __shared__ char psm[];
    const uint32_t raw = smem_u32(psm);
    const uint32_t abase = (raw + 1023u) & ~1023u;
    char* cbase = psm + (abase - raw);
    const uint32_t aA = abase;
    const uint32_t aW0 = abase + 65536u, aW1 = abase + 131072u;

    const int tid = threadIdx.x, wid = tid >> 5, lane = tid & 31;
    const int mi = wid >> 1, ni = wid & 1;
    const int i0 = blockIdx.x * 128, j0 = blockIdx.y * 128;

    const int mat = lane >> 3, lr = lane & 7;
    const int arow = (mat & 1) * 8 + lr;
    const int asel = mat >> 1;
    const int brow = ((mat >> 1) << 3) + lr;
    const int bsel = mat & 1;

    const uint4* Wq4 = reinterpret_cast<const uint4*>(Wq16);
    const uint4* Wk4 = reinterpret_cast<const uint4*>(Wk16);
    const uint4* Wv4 = reinterpret_cast<const uint4*>(Wv16);

    // async weight loads first (group1: Wq, group2: Wk)
    #pragma unroll
    for (int t = 0; t < 16; t++) {
        int idx = tid + t * 256;
        int r = idx >> 5, c = idx & 31;
        cpa16(tadr(aW0, r, c, 4), Wq4 + (size_t)(j0 + r)*32 + c);
    }
    CPA_COMMIT();
    #pragma unroll
    for (int t = 0; t < 16; t++) {
        int idx = tid + t * 256;
        int r = idx >> 5, c = idx & 31;
        cpa16(tadr(aW1, r, c, 4), Wk4 + (size_t)(j0 + r)*32 + c);
    }
    CPA_COMMIT();

    // A tile: fp32 LDG -> in-register fp16 convert -> swizzled STS
    {
        const float4* Af4 = reinterpret_cast<const float4*>(Asrc) + (size_t)i0 * 64;
        #pragma unroll
        for (int t = 0; t < 16; t++) {
            int idx = tid + t * 256;      // 0..4095 16B-f16 chunks
            int r = idx >> 5, c = idx & 31;
            float4 v0 = Af4[(size_t)r*64 + c*2];
            float4 v1 = Af4[(size_t)r*64 + c*2 + 1];
            uint4 h;
            h.x = pack_h2(v0.x, v0.y); h.y = pack_h2(v0.z, v0.w);
            h.z = pack_h2(v1.x, v1.y); h.w = pack_h2(v1.z, v1.w);
            sts128(tadr(aA, r, c, 4), h);
        }
    }

    float oacc[2][8][4];

    // ---- Q phase ----
    CPA_WAIT(1);                         // Wq done
    __syncthreads();                     // A STS visible too
    mma_phase(aA, aW0, mi, ni, arow, asel, brow, bsel, oacc);
    __syncthreads();
    #pragma unroll
    for (int t = 0; t < 16; t++) {
        int idx = tid + t * 256;
        int r = idx >> 5, c = idx & 31;
        cpa16(tadr(aW0, r, c, 4), Wv4 + (size_t)(j0 + r)*32 + c);
    }
    CPA_COMMIT();
    epi_rowmajor(oacc, bq, Qh, q0, qscale, i0, j0, mi, ni, lane);

    // ---- K phase ----
    CPA_WAIT(1);                         // Wk done (Wv in flight)
    __syncthreads();
    mma_phase(aA, aW1, mi, ni, arow, asel, brow, bsel, oacc);
    epi_rowmajor(oacc, bk, Kh, k0, 1.0f, i0, j0, mi, ni, lane);

    // ---- V phase ----
    CPA_WAIT(0);                         // Wv done
    __syncthreads();
    mma_phase(aA, aW0, mi, ni, arow, asel, brow, bsel, oacc);

    {
        float* st = reinterpret_cast<float*>(cbase + 131072);
        const int r0 = lane >> 2, cb = lane & 3;
        const int b = i0 >> 12, s0 = i0 & 4095;
        uint4* V4o = reinterpret_cast<uint4*>(Vt);
        #pragma unroll
        for (int p = 0; p < 2; p++) {
            __syncthreads();
            if ((mi >> 1) == p) {
                #pragma unroll
                for (int m2 = 0; m2 < 2; m2++)
                    #pragma unroll
                    for (int nf = 0; nf < 8; nf++) {
                        int r = (mi & 1)*32 + m2*16 + r0;
                        int c = ni*64 + nf*8 + cb*2;
                        float b0v = bv[j0 + c], b1v = bv[j0 + c + 1];
                        st[r*129 + c]       = oacc[m2][nf][0] + b0v;
                        st[r*129 + c + 1]   = oacc[m2][nf][1] + b1v;
                        st[(r+8)*129 + c]   = oacc[m2][nf][2] + b0v;
                        st[(r+8)*129 + c+1] = oacc[m2][nf][3] + b1v;
                    }
            }
            __syncthreads();
            #pragma unroll
            for (int t = 0; t < 4; t++) {
                int idx = tid + t * 256;
                int dl = idx >> 3, sc = idx & 7;
                uint32_t hh[4];
                #pragma unroll
                for (int e = 0; e < 4; e++)
                    hh[e] = pack_h2(st[(sc*8 + 2*e)*129 + dl],
                                    st[(sc*8 + 2*e + 1)*129 + dl]);
                V4o[((size_t)(b*DD + j0 + dl))*512 + (s0 >> 3) + p*8 + sc] =
                    make_uint4(hh[0], hh[1], hh[2], hh[3]);
            }
        }
    }
}

// ---------------------------------------------------------------------------
// flash_mma: reg-P M-split flash + fused Wo epilogue, early half-Wo prefetch
// into the dead K0/V0 buffers during the last key tile, q0/k0 preloaded.
// SMEM: Q 64K | K ping-pong 2x32K | V ping-pong 2x32K = 192K (Wo reuses K/V)
// (frozen from the 258.6 us round)
// ---------------------------------------------------------------------------
#define OFF_Q    0u
#define OFF_K0   65536u
#define OFF_K1   98304u
#define OFF_V0   131072u
#define OFF_V1   163840u
#define FL_SMEM  (196608 + 1024)

__global__ __launch_bounds__(256, 1) void flash_mma(
    const __half* __restrict__ Qh_, const __half* __restrict__ Kh_,
    const __half* __restrict__ Vth_, const __half* __restrict__ Wo16_,
    const float* __restrict__ q0g, const float* __restrict__ k0g,
    const float* __restrict__ bo, float* __restrict__ outF)
{
    extern __shared__ char fsm[];
    const uint32_t raw = smem_u32(fsm);
    const uint32_t abase = (raw + 1023u) & ~1023u;
    const uint32_t aQ = abase + OFF_Q;
    const uint32_t aK[2] = { abase + OFF_K0, abase + OFF_K1 };
    const uint32_t aV[2] = { abase + OFF_V0, abase + OFF_V1 };
    const uint32_t aWo = abase + OFF_K0;

    const int tid = threadIdx.x, wid = tid >> 5, lane = tid & 31;
    const int b = blockIdx.y, i0 = blockIdx.x * 128;

    const int mat = lane >> 3, lr = lane & 7;
    const int arow = (mat & 1) * 8 + lr;
    const int asel = mat >> 1;
    const int brow = ((mat >> 1) << 3) + lr;
    const int bsel = mat & 1;

    const uint4* Qg4 = reinterpret_cast<const uint4*>(Qh_) + ((size_t)(b*SS + i0)) * 32;
    const uint4* Kg4 = reinterpret_cast<const uint4*>(Kh_) + (size_t)b*SS*32;
    const uint4* Vg4 = reinterpret_cast<const uint4*>(Vth_) + (size_t)b*DD*512;
    const uint4* Wo4 = reinterpret_cast<const uint4*>(Wo16_);

    const int r0 = lane >> 2, cb = lane & 3;
    size_t g0 = (size_t)b*SS + i0 + wid*16 + r0;
    size_t g1 = g0 + 8;
    float q0v0 = q0g[g0], k0v0 = k0g[g0];
    float q0v1 = q0g[g1], k0v1 = k0g[g1];

    #pragma unroll
    for (int t = 0; t < 16; t++) {
        int idx = tid + t * 256;
        int r = idx >> 5, c = idx & 31;
        cpa16(tadr(aQ, r, c, 4), Qg4 + (size_t)r*32 + c);
    }
    CPA_COMMIT();
    #pragma unroll
    for (int t = 0; t < 8; t++) {
        int idx = tid + t * 256;
        int r = idx >> 5, c = idx & 31;
        cpa16(tadr(aK[0], r, c, 4), Kg4 + (size_t)r*32 + c);
    }
    CPA_COMMIT();
    #pragma unroll
    for (int t = 0; t < 8; t++) {
        int idx = tid + t * 256;
        int r = idx >> 3, c = idx & 7;
        cpa16(tadr(aV[0], r, c, 1), Vg4 + (size_t)r*512 + c);
    }
    CPA_COMMIT();

    float oacc[32][4];
    #pragma unroll
    for (int nf = 0; nf < 32; nf++)
        #pragma unroll
        for (int j = 0; j < 4; j++) oacc[nf][j] = 0.0f;
    float lsum0 = 0.0f, lsum1 = 0.0f;

    const int qrow = wid*16 + arow;

    for (int kt = 0; kt < SS/64; kt++) {
        const int buf = kt & 1;
        __syncthreads();
        if (kt + 1 < SS/64) {
            const int nb = buf ^ 1;
            #pragma unroll
            for (int t = 0; t < 8; t++) {
                int idx = tid + t * 256;
                int r = idx >> 5, c = idx & 31;
                cpa16(tadr(aK[nb], r, c, 4), Kg4 + (size_t)((kt+1)*64 + r)*32 + c);
            }
            CPA_COMMIT();
            #pragma unroll
            for (int t = 0; t < 8; t++) {
                int idx = tid + t * 256;
                int r = idx >> 3, c = idx & 7;
                cpa16(tadr(aV[nb], r, c, 1), Vg4 + (size_t)r*512 + (kt+1)*8 + c);
            }
            CPA_COMMIT();
            CPA_WAIT(2);
        } else {
            #pragma unroll
            for (int t = 0; t < 16; t++) {
                int idx = tid + t * 256;
                int rr = idx >> 5, c = idx & 31;
                int r = ((rr & 64) << 1) | (rr & 63);
                cpa16(tadr(aWo, r, c, 4), Wo4 + (size_t)r*32 + c);
            }
            CPA_COMMIT();
            CPA_WAIT(1);
        }
        __syncthreads();

        // ---- Phase A: MMA1 keys 0..31 ----
        float sa[4][4];
        #pragma unroll
        for (int n8 = 0; n8 < 4; n8++)
            #pragma unroll
            for (int j = 0; j < 4; j++) sa[n8][j] = 0.0f;

        #pragma unroll
        for (int ks = 0; ks < 16; ks++) {
            uint32_t a0,a1,a2,a3;
            LDMX4(a0,a1,a2,a3, tadr(aQ, qrow, 2*ks + asel, 4));
            #pragma unroll
            for (int n16 = 0; n16 < 2; n16++) {
                uint32_t b0,b1,b2,b3;
                LDMX4(b0,b1,b2,b3, tadr(aK[buf], n16*16 + brow, 2*ks + bsel, 4));
                MMA16816(sa[n16*2  ], a0,a1,a2,a3, b0,b1);
                MMA16816(sa[n16*2+1], a0,a1,a2,a3, b2,b3);
            }
        }

        uint32_t pfl[2][4];
        #pragma unroll
        for (int n8 = 0; n8 < 4; n8++) {
            float e0 = ex2f(sa[n8][0]);
            float e1 = ex2f(sa[n8][1]);
            float e2 = ex2f(sa[n8][2]);
            float e3 = ex2f(sa[n8][3]);
            lsum0 += e0 + e1;
            lsum1 += e2 + e3;
            pfl[n8 >> 1][(n8 & 1)*2    ] = pack_h2(e0, e1);
            pfl[n8 >> 1][(n8 & 1)*2 + 1] = pack_h2(e2, e3);
        }

        // ---- Phase B (fused): MMA1 keys 32..63 + MMA2 ks 0..1 ----
        float sb[4][4];
        #pragma unroll
        for (int n8 = 0; n8 < 4; n8++)
            #pragma unroll
            for (int j = 0; j < 4; j++) sb[n8][j] = 0.0f;

        #pragma unroll
        for (int ks = 0; ks < 16; ks++) {
            uint32_t a0,a1,a2,a3;
            LDMX4(a0,a1,a2,a3, tadr(aQ, qrow, 2*ks + asel, 4));
            #pragma unroll
            for (int n16 = 0; n16 < 2; n16++) {
                uint32_t b0,b1,b2,b3;
                LDMX4(b0,b1,b2,b3, tadr(aK[buf], (n16+2)*16 + brow, 2*ks + bsel, 4));
                MMA16816(sb[n16*2  ], a0,a1,a2,a3, b0,b1);
                MMA16816(sb[n16*2+1], a0,a1,a2,a3, b2,b3);
            }
            #pragma unroll
            for (int u = 0; u < 2; u++) {
                const int vidx = ks*2 + u;
                const int k2 = vidx >> 4;
                const int nv = vidx & 15;
                uint32_t b0,b1,b2,b3;
                LDMX4(b0,b1,b2,b3, tadr(aV[buf], nv*16 + brow, 2*k2 + bsel, 1));
                MMA16816(oacc[nv*2  ], pfl[k2][0],pfl[k2][1],pfl[k2][2],pfl[k2][3], b0,b1);
                MMA16816(oacc[nv*2+1], pfl[k2][0],pfl[k2][1],pfl[k2][2],pfl[k2][3], b2,b3);
            }
        }

        uint32_t pfh[2][4];
        #pragma unroll
        for (int n8 = 0; n8 < 4; n8++) {
            float e0 = ex2f(sb[n8][0]);
            float e1 = ex2f(sb[n8][1]);
            float e2 = ex2f(sb[n8][2]);
            float e3 = ex2f(sb[n8][3]);
            lsum0 += e0 + e1;
            lsum1 += e2 + e3;
            pfh[n8 >> 1][(n8 & 1)*2    ] = pack_h2(e0, e1);
            pfh[n8 >> 1][(n8 & 1)*2 + 1] = pack_h2(e2, e3);
        }

        #pragma unroll
        for (int k2 = 0; k2 < 2; k2++) {
            #pragma unroll
            for (int nv = 0; nv < 16; nv++) {
                uint32_t b0,b1,b2,b3;
                LDMX4(b0,b1,b2,b3, tadr(aV[buf], nv*16 + brow, 2*(k2+2) + bsel, 1));
                MMA16816(oacc[nv*2  ], pfh[k2][0],pfh[k2][1],pfh[k2][2],pfh[k2][3], b0,b1);
                MMA16816(oacc[nv*2+1], pfh[k2][0],pfh[k2][1],pfh[k2][2],pfh[k2][3], b2,b3);
            }
        }
    }

    // ---- fused Wo epilogue ----
    __syncthreads();
    #pragma unroll
    for (int t = 0; t < 16; t++) {
        int idx = tid + t * 256;
        int rr = idx >> 5, c = idx & 31;
        int r = (((rr & 64) << 1) | (rr & 63)) + 64;
        cpa16(tadr(aWo, r, c, 4), Wo4 + (size_t)r*32 + c);
    }
    CPA_COMMIT();

    lsum0 += __shfl_xor_sync(0xffffffff, lsum0, 1);
    lsum0 += __shfl_xor_sync(0xffffffff, lsum0, 2);
    lsum1 += __shfl_xor_sync(0xffffffff, lsum1, 1);
    lsum1 += __shfl_xor_sync(0xffffffff, lsum1, 2);

    float mf0 = (q0v0 != 0.0f && k0v0 != 0.0f) ? (1.0f / lsum0) : 0.0f;
    float mf1 = (q0v1 != 0.0f && k0v1 != 0.0f) ? (1.0f / lsum1) : 0.0f;

    uint32_t af[16][4];
    #pragma unroll
    for (int nf = 0; nf < 32; nf++) {
        const int ks = nf >> 1;
        af[ks][(nf & 1)*2    ] = pack_h2(oacc[nf][0]*mf0, oacc[nf][1]*mf0);
        af[ks][(nf & 1)*2 + 1] = pack_h2(oacc[nf][2]*mf1, oacc[nf][3]*mf1);
    }

    float outa[32][4];
    #pragma unroll
    for (int nf = 0; nf < 32; nf++)
        #pragma unroll
        for (int j = 0; j < 4; j++) outa[nf][j] = 0.0f;

    CPA_WAIT(0);
    __syncthreads();

    #pragma unroll 4
    for (int ks = 0; ks < 16; ks++) {
        #pragma unroll
        for (int n16 = 0; n16 < 16; n16++) {
            uint32_t b0,b1,b2,b3;
            LDMX4(b0,b1,b2,b3, tadr(aWo, n16*16 + brow, 2*ks + bsel, 4));
            MMA16816(outa[n16*2  ], af[ks][0],af[ks][1],af[ks][2],af[ks][3], b0,b1);
            MMA16816(outa[n16*2+1], af[ks][0],af[ks][1],af[ks][2],af[ks][3], b2,b3);
        }
    }

    float2* O0 = reinterpret_cast<float2*>(outF + g0*DD);
    float2* O1 = reinterpret_cast<float2*>(outF + g1*DD);
    #pragma unroll
    for (int nf = 0; nf < 32; nf++) {
        int c = (nf >> 1)*16 + (nf & 1)*8 + cb*2;
        float b0v = bo[c], b1v = bo[c + 1];
        O0[((unsigned)c) >> 1] = make_float2(outa[nf][0] + b0v, outa[nf][1] + b1v);
        O1[((unsigned)c) >> 1] = make_float2(outa[nf][2] + b0v, outa[nf][3] + b1v);
    }
}

// ---------------------------------------------------------------------------
extern "C" void kernel_launch(void* const* d_in, const int* in_sizes, int n_in,
                              void* d_out, int out_size)
{
    const float* src = (const float*)d_in[0];
    const float* Wq  = (const float*)d_in[1];
    const float* bq  = (const float*)d_in[2];
    const float* Wk  = (const float*)d_in[3];
    const float* bk  = (const float*)d_in[4];
    const float* Wv  = (const float*)d_in[5];
    const float* bv  = (const float*)d_in[6];
    const float* Wo  = (const float*)d_in[7];
    const float* bo  = (const float*)d_in[8];
    float* out = (float*)d_out;

    __half *pWq,*pWk,*pWv,*pWo,*pQ,*pK,*pV;
    float *pq0,*pk0;
    cudaGetSymbolAddress((void**)&pWq, g_Wq16);
    cudaGetSymbolAddress((void**)&pWk, g_Wk16);
    cudaGetSymbolAddress((void**)&pWv, g_Wv16);
    cudaGetSymbolAddress((void**)&pWo, g_Wo16);
    cudaGetSymbolAddress((void**)&pQ, g_Qh);
    cudaGetSymbolAddress((void**)&pK, g_Kh);
    cudaGetSymbolAddress((void**)&pV, g_Vth);
    cudaGetSymbolAddress((void**)&pq0, g_q0);
    cudaGetSymbolAddress((void**)&pk0, g_k0);

    cvt_w4<<<dim3(W_N4/256, 4), 256>>>(
        (const float4*)Wq, (const float4*)Wk, (const float4*)Wv, (const float4*)Wo,
        (uint2*)pWq, (uint2*)pWk, (uint2*)pWv, (uint2*)pWo);

    cudaFuncSetAttribute(proj_qkv, cudaFuncAttributeMaxDynamicSharedMemorySize, QKV_SMEM);
    // Q scale = (1/sqrt(256)) * log2(e) -> softmax becomes raw exp2
    proj_qkv<<<dim3(NN/128, 2), 256, QKV_SMEM>>>(
        src, pWq, pWk, pWv, bq, bk, bv, pQ, pK, pV, pq0, pk0, 0.0901684761047f);

    cudaFuncSetAttribute(flash_mma, cudaFuncAttributeMaxDynamicSharedMemorySize, FL_SMEM);
    flash_mma<<<dim3(SS/128, BB), 256, FL_SMEM>>>(pQ, pK, pV, pWo, pq0, pk0, bo, out);
}